// round 2
// baseline (speedup 1.0000x reference)
#include <cuda_runtime.h>

// SORF, three kernels:
//  prep:  zero out, group atoms by charge
//  gemv:  proj[atom][:] = (1/16) * rep[atom][:] @ reductors[s]   (packed f32x2 FMA)
//  fwht:  out[m] += (1/64) * sum_j alpha . cos(FWHT_sign(proj) + bias)

#define NATOMS 2048           // M*A
#define ATOMS_A 8             // atoms per gemv CTA
#define ATOMS_B 4             // atoms per fwht CTA

__device__ int g_count[4];
__device__ int g_list[4 * NATOMS];
__device__ float g_proj[NATOMS * 256];

__global__ void prep_kernel(const int* __restrict__ charges, float* __restrict__ out) {
    int tid = threadIdx.x;
    if (tid < 4) g_count[tid] = 0;
    if (tid < 32) out[tid] = 0.0f;
    __syncthreads();
    for (int i = tid; i < NATOMS; i += 256) {
        int s = charges[i];
        int idx = atomicAdd(&g_count[s], 1);
        g_list[s * NATOMS + idx] = i;
    }
}

__device__ __forceinline__ void ffma2(unsigned long long& acc, unsigned long long a, unsigned long long b) {
    asm("fma.rn.f32x2 %0, %1, %2, %0;" : "+l"(acc) : "l"(a), "l"(b));
}
__device__ __forceinline__ unsigned long long pack2(float a, float b) {
    unsigned long long r; asm("mov.b64 %0, {%1, %2};" : "=l"(r) : "f"(a), "f"(b)); return r;
}
__device__ __forceinline__ float2 unpack2(unsigned long long v) {
    float2 r; asm("mov.b64 {%0, %1}, %2;" : "=f"(r.x), "=f"(r.y) : "l"(v)); return r;
}

// ---------------------------------------------------------------- GEMV
__global__ void __launch_bounds__(256) gemv_kernel(
    const float* __restrict__ rep,
    const float* __restrict__ reductors)
{
    const int s = blockIdx.y;
    const int n = g_count[s];
    const int start = blockIdx.x * ATOMS_A;
    if (start >= n) return;

    __shared__ unsigned long long repdupS[ATOMS_A * 512];  // {v,v} pairs, 32 KB
    __shared__ int atomsS[ATOMS_A];

    const int tid = threadIdx.x;
    if (tid < ATOMS_A) atomsS[tid] = (start + tid < n) ? g_list[s * NATOMS + start + tid] : -1;
    __syncthreads();

    // fill duplicated rep tile
    {
        const float4* src = (const float4*)rep;
        #pragma unroll
        for (int it = 0; it < 4; ++it) {
            int idx = tid + 256 * it;        // 1024 float4 slots = 8 atoms * 128
            int ai = idx >> 7, q = idx & 127;
            int atom = atomsS[ai];
            float4 v = (atom >= 0) ? src[(size_t)atom * 128 + q] : make_float4(0.f, 0.f, 0.f, 0.f);
            unsigned long long* d = repdupS + ai * 512 + q * 4;
            d[0] = pack2(v.x, v.x); d[1] = pack2(v.y, v.y);
            d[2] = pack2(v.z, v.z); d[3] = pack2(v.w, v.w);
        }
    }
    __syncthreads();

    const int c2 = tid & 127;   // column pair: cols 2*c2, 2*c2+1
    const int ag = tid >> 7;    // atom group: atoms 4*ag .. 4*ag+3

    unsigned long long acc[4] = {0ull, 0ull, 0ull, 0ull};
    const unsigned long long* rbase = (const unsigned long long*)reductors + (size_t)s * 65536 + c2;

    unsigned long long cur[4], nxt[4];
    #pragma unroll
    for (int k = 0; k < 4; ++k) cur[k] = rbase[k * 128];

    #pragma unroll 1
    for (int r = 0; r < 512; r += 4) {
        if (r + 4 < 512) {
            #pragma unroll
            for (int k = 0; k < 4; ++k) nxt[k] = rbase[(size_t)(r + 4 + k) * 128];
        }
        const ulonglong2* rp = (const ulonglong2*)repdupS;
        #pragma unroll
        for (int a = 0; a < 4; ++a) {
            int base = (ag * 4 + a) * 256 + (r >> 1);
            ulonglong2 p0 = rp[base];       // broadcast LDS.128: {rep_r,rep_r},{rep_r+1,rep_r+1}
            ulonglong2 p1 = rp[base + 1];
            ffma2(acc[a], p0.x, cur[0]);
            ffma2(acc[a], p0.y, cur[1]);
            ffma2(acc[a], p1.x, cur[2]);
            ffma2(acc[a], p1.y, cur[3]);
        }
        #pragma unroll
        for (int k = 0; k < 4; ++k) cur[k] = nxt[k];
    }

    #pragma unroll
    for (int a = 0; a < 4; ++a) {
        int atom = atomsS[ag * 4 + a];
        if (atom >= 0) {
            float2 v = unpack2(acc[a]);
            ((float2*)g_proj)[(size_t)atom * 128 + c2] = make_float2(v.x * 0.0625f, v.y * 0.0625f);
        }
    }
}

// ---------------------------------------------------------------- FWHT + cos dot
#define BFLY(a, b) do { float t_ = (a); (a) = t_ + (b); (b) = t_ - (b); } while (0)
__device__ __forceinline__ float sgnx(float x, float d) {
    return __uint_as_float(__float_as_uint(x) ^ (__float_as_uint(d) & 0x80000000u));
}

__global__ void __launch_bounds__(256) fwht_kernel(
    const float* __restrict__ Dmat,
    const float* __restrict__ bias,
    const float* __restrict__ alpha,
    float* __restrict__ out)
{
    const int s = blockIdx.y;
    const int n = g_count[s];
    const int start = blockIdx.x * ATOMS_B;
    if (start >= n) return;

    __shared__ float projS[ATOMS_B * 256];
    __shared__ int atomsS[ATOMS_B];
    __shared__ float wpartS[ATOMS_B];

    const int tid = threadIdx.x;
    const int lane = tid & 31;
    const int w = tid >> 5;

    if (tid < ATOMS_B) atomsS[tid] = (start + tid < n) ? g_list[s * NATOMS + start + tid] : -1;
    __syncthreads();
    {
        int ai = tid >> 6, q = tid & 63;   // 4 atoms x 64 float4
        int atom = atomsS[ai];
        float4 v = (atom >= 0) ? __ldg((const float4*)g_proj + (size_t)atom * 64 + q)
                               : make_float4(0.f, 0.f, 0.f, 0.f);
        ((float4*)projS)[tid] = v;
    }
    __syncthreads();

    const int ai = w >> 1;       // atom slot
    const int jh = w & 1;        // stack half: j in [16*jh, 16*jh+16)
    const int atom = atomsS[ai];
    float partial = 0.f;

    if (atom >= 0) {
        const float4* pj4 = (const float4*)(projS + ai * 256);
        const float4 xa4 = pj4[lane];        // p = 4*lane + c      (invariant over j)
        const float4 xb4 = pj4[lane + 32];   // p = 128 + 4*lane + c

        const float* dbase = Dmat + (size_t)s * 8192 + 4 * lane;
        const float* bbase = bias + (size_t)s * 8192 + 4 * lane;
        const float4* abase = (const float4*)alpha + lane;

        const float sg0 = (lane & 1) ? -1.f : 1.f;
        const float sg1 = (lane & 2) ? -1.f : 1.f;
        const float sg2 = (lane & 4) ? -1.f : 1.f;
        const float sg3 = (lane & 8) ? -1.f : 1.f;
        const float sg4 = (lane & 16) ? -1.f : 1.f;

        for (int j = 16 * jh; j < 16 * jh + 16; ++j) {
            float4 d0 = __ldg((const float4*)(dbase + j * 256));
            float4 d1 = __ldg((const float4*)(dbase + j * 256 + 128));
            float x0 = sgnx(xa4.x, d0.x), x1 = sgnx(xa4.y, d0.y);
            float x2 = sgnx(xa4.z, d0.z), x3 = sgnx(xa4.w, d0.w);
            float x4 = sgnx(xb4.x, d1.x), x5 = sgnx(xb4.y, d1.y);
            float x6 = sgnx(xb4.z, d1.z), x7 = sgnx(xb4.w, d1.w);

            // register butterflies: h=1, h=2, h=128
            BFLY(x0, x1); BFLY(x2, x3); BFLY(x4, x5); BFLY(x6, x7);
            BFLY(x0, x2); BFLY(x1, x3); BFLY(x4, x6); BFLY(x5, x7);
            BFLY(x0, x4); BFLY(x1, x5); BFLY(x2, x6); BFLY(x3, x7);

            // cross-lane butterflies: h = 4,8,16,32,64
            #define SSTAGE(m, sg)                                                  \
                x0 = fmaf(x0, sg, __shfl_xor_sync(0xffffffffu, x0, m));            \
                x1 = fmaf(x1, sg, __shfl_xor_sync(0xffffffffu, x1, m));            \
                x2 = fmaf(x2, sg, __shfl_xor_sync(0xffffffffu, x2, m));            \
                x3 = fmaf(x3, sg, __shfl_xor_sync(0xffffffffu, x3, m));            \
                x4 = fmaf(x4, sg, __shfl_xor_sync(0xffffffffu, x4, m));            \
                x5 = fmaf(x5, sg, __shfl_xor_sync(0xffffffffu, x5, m));            \
                x6 = fmaf(x6, sg, __shfl_xor_sync(0xffffffffu, x6, m));            \
                x7 = fmaf(x7, sg, __shfl_xor_sync(0xffffffffu, x7, m));
            SSTAGE(1, sg0) SSTAGE(2, sg1) SSTAGE(4, sg2) SSTAGE(8, sg3) SSTAGE(16, sg4)
            #undef SSTAGE

            float4 b0 = __ldg((const float4*)(bbase + j * 256));
            float4 b1 = __ldg((const float4*)(bbase + j * 256 + 128));
            float4 a0 = __ldg(abase + j * 64);
            float4 a1 = __ldg(abase + j * 64 + 32);
            partial = fmaf(__cosf(x0 + b0.x), a0.x, partial);
            partial = fmaf(__cosf(x1 + b0.y), a0.y, partial);
            partial = fmaf(__cosf(x2 + b0.z), a0.z, partial);
            partial = fmaf(__cosf(x3 + b0.w), a0.w, partial);
            partial = fmaf(__cosf(x4 + b1.x), a1.x, partial);
            partial = fmaf(__cosf(x5 + b1.y), a1.y, partial);
            partial = fmaf(__cosf(x6 + b1.z), a1.z, partial);
            partial = fmaf(__cosf(x7 + b1.w), a1.w, partial);
        }

        #pragma unroll
        for (int o = 16; o; o >>= 1) partial += __shfl_xor_sync(0xffffffffu, partial, o);
    }

    if (jh == 1 && lane == 0) wpartS[ai] = partial;
    __syncthreads();
    if (jh == 0 && lane == 0 && atom >= 0)
        atomicAdd(out + (atom >> 6), (partial + wpartS[ai]) * 0.015625f);  // FEAT_NORM = 1/64
}

extern "C" void kernel_launch(void* const* d_in, const int* in_sizes, int n_in,
                              void* d_out, int out_size) {
    (void)in_sizes; (void)n_in; (void)out_size;
    const float* rep       = (const float*)d_in[0];
    const int*   charges   = (const int*)d_in[1];
    const float* reductors = (const float*)d_in[2];
    const float* Dmat      = (const float*)d_in[3];
    const float* bias      = (const float*)d_in[4];
    const float* alpha     = (const float*)d_in[5];
    float* out = (float*)d_out;

    prep_kernel<<<1, 256>>>(charges, out);
    gemv_kernel<<<dim3(NATOMS / ATOMS_A, 4), 256>>>(rep, reductors);
    fwht_kernel<<<dim3(NATOMS / ATOMS_B, 4), 256>>>(Dmat, bias, alpha, out);
}

// round 5
// speedup vs baseline: 1.0787x; 1.0787x over previous
#include <cuda_runtime.h>

// SORF fused: out[m] = (1/64) * sum_a alpha . cos( (1/16) H (D_s ⊙ (rep[m,a] @ red[s])) + bias_s ),
// s = charges[m,a]. Atoms grouped by charge; one fused kernel does GEMV (f32x2, prefetched)
// then per-warp FWHT(256) + cos-dot, all smem/register resident.

#define ATOMS 8
#define NATOMS 2048           // M*A
#define NBLK (NATOMS / ATOMS) // 256

__device__ int g_count[4];
__device__ int g_list[4 * NATOMS];

// ---- fast prep: warp-ballot compaction, no global atomics ----
__global__ void prep_kernel(const int* __restrict__ charges, float* __restrict__ out) {
    const int tid = threadIdx.x;
    const int lane = tid & 31;
    const int w = tid >> 5;          // warp w handles charge s = w
    if (tid < 32) out[tid] = 0.0f;
    if (w >= 4) return;
    int cnt = 0;
    const unsigned lt = (1u << lane) - 1u;
    for (int base = 0; base < NATOMS; base += 32) {
        int c = charges[base + lane];
        unsigned m = __ballot_sync(0xffffffffu, c == w);
        if (c == w) g_list[w * NATOMS + cnt + __popc(m & lt)] = base + lane;
        cnt += __popc(m);
    }
    if (lane == 0) g_count[w] = cnt;
}

typedef unsigned long long ull;
__device__ __forceinline__ void ffma2(ull& acc, ull a, ull b) {
    asm("fma.rn.f32x2 %0, %1, %2, %0;" : "+l"(acc) : "l"(a), "l"(b));
}
__device__ __forceinline__ ull pack2(float a, float b) {
    ull r; asm("mov.b64 %0, {%1, %2};" : "=l"(r) : "f"(a), "f"(b)); return r;
}
__device__ __forceinline__ float2 unpack2(ull v) {
    float2 r; asm("mov.b64 {%0, %1}, %2;" : "=f"(r.x), "=f"(r.y) : "l"(v)); return r;
}

#define BFLY(a, b) do { float t_ = (a); (a) = t_ + (b); (b) = t_ - (b); } while (0)

__global__ void __launch_bounds__(256) sorf_kernel(
    const float* __restrict__ rep,
    const float* __restrict__ reductors,
    const float* __restrict__ Dmat,
    const float* __restrict__ bias,
    const float* __restrict__ alpha,
    float* __restrict__ out)
{
    const int s = blockIdx.y;
    const int n = g_count[s];
    const int start = blockIdx.x * ATOMS;
    if (start >= n) return;
    const int cnt = min(ATOMS, n - start);

    // 32 KB region: phase 1 = duplicated rep pairs {v,v}; phase 2 = bias (overlaid)
    __shared__ __align__(16) char bufS[ATOMS * 512 * 8];
    __shared__ float projS[ATOMS * 256];      // 8 KB
    __shared__ unsigned dbitsS[256];          // 1 KB sign bits (32 stacks x 8 words)
    __shared__ int atomsS[ATOMS];

    const int tid = threadIdx.x;
    const int lane = tid & 31;
    const int w = tid >> 5;

    if (tid < ATOMS) atomsS[tid] = (tid < cnt) ? g_list[s * NATOMS + start + tid] : -1;
    __syncthreads();

    // fill duplicated rep tile: repdup[atom][r] = {rep_r, rep_r}
    {
        ull* repdup = (ull*)bufS;
        const float4* src = (const float4*)rep;
        #pragma unroll
        for (int it = 0; it < 4; ++it) {
            int idx = tid + 256 * it;            // 1024 float4 slots = 8 atoms * 128
            int ai = idx >> 7, q = idx & 127;
            int atom = atomsS[ai];
            float4 v = (atom >= 0) ? src[(size_t)atom * 128 + q] : make_float4(0.f, 0.f, 0.f, 0.f);
            ull* d = repdup + ai * 512 + q * 4;
            d[0] = pack2(v.x, v.x); d[1] = pack2(v.y, v.y);
            d[2] = pack2(v.z, v.z); d[3] = pack2(v.w, v.w);
        }
    }
    __syncthreads();

    // ---------------- Phase 1: proj = (1/16) * rep @ red[s], f32x2, 2-step prefetch
    {
        const int c2 = tid & 127;   // column pair (cols 2*c2, 2*c2+1)
        const int ag = tid >> 7;    // atoms 4*ag .. 4*ag+3
        ull acc[4] = {0ull, 0ull, 0ull, 0ull};
        const ull* rbase = (const ull*)reductors + (size_t)s * 65536 + c2;
        const ulonglong2* rp = (const ulonglong2*)bufS;

        ull buf0[4], buf1[4];
        #pragma unroll
        for (int k = 0; k < 4; ++k) buf0[k] = rbase[(size_t)k * 128];
        #pragma unroll
        for (int k = 0; k < 4; ++k) buf1[k] = rbase[(size_t)(4 + k) * 128];

        #pragma unroll 1
        for (int r = 0; r < 512; r += 8) {
            ull c0[4], c1[4];
            #pragma unroll
            for (int k = 0; k < 4; ++k) c0[k] = buf0[k];
            if (r + 8 < 512) {
                #pragma unroll
                for (int k = 0; k < 4; ++k) buf0[k] = rbase[(size_t)(r + 8 + k) * 128];
            }
            #pragma unroll
            for (int a = 0; a < 4; ++a) {
                int base = (ag * 4 + a) * 256 + (r >> 1);
                ulonglong2 p0 = rp[base];
                ulonglong2 p1 = rp[base + 1];
                ffma2(acc[a], p0.x, c0[0]); ffma2(acc[a], p0.y, c0[1]);
                ffma2(acc[a], p1.x, c0[2]); ffma2(acc[a], p1.y, c0[3]);
            }
            #pragma unroll
            for (int k = 0; k < 4; ++k) c1[k] = buf1[k];
            if (r + 12 < 512) {
                #pragma unroll
                for (int k = 0; k < 4; ++k) buf1[k] = rbase[(size_t)(r + 12 + k) * 128];
            }
            #pragma unroll
            for (int a = 0; a < 4; ++a) {
                int base = (ag * 4 + a) * 256 + ((r + 4) >> 1);
                ulonglong2 p0 = rp[base];
                ulonglong2 p1 = rp[base + 1];
                ffma2(acc[a], p0.x, c1[0]); ffma2(acc[a], p0.y, c1[1]);
                ffma2(acc[a], p1.x, c1[2]); ffma2(acc[a], p1.y, c1[3]);
            }
        }
        __syncthreads();   // all reads of repdup done before bias overlays it
        #pragma unroll
        for (int a = 0; a < 4; ++a) {
            float2 v = unpack2(acc[a]);
            ((float2*)projS)[(ag * 4 + a) * 128 + c2] = make_float2(v.x * 0.0625f, v.y * 0.0625f);
        }
    }

    // bias -> smem (overlay), D sign bits via ballot
    {
        float4* dst = (float4*)bufS;
        const float4* src = (const float4*)(bias + (size_t)s * 8192);
        #pragma unroll
        for (int it = 0; it < 8; ++it) dst[tid + 256 * it] = src[tid + 256 * it];
        const float* dsrc = Dmat + (size_t)s * 8192;
        #pragma unroll 1
        for (int k = 0; k < 32; ++k) {
            int word = w * 32 + k;
            float dv = dsrc[word * 32 + lane];
            unsigned b = __ballot_sync(0xffffffffu, dv < 0.0f);
            if (lane == 0) dbitsS[word] = b;
        }
    }
    __syncthreads();

    // ---------------- Phase 2: warp w = atom w; 32 stacks of FWHT(256) + cos-dot
    // x[c] holds p = 4*lane+c ; x[4+c] holds p = 128+4*lane+c
    if (w < cnt) {
        const float4* pj4 = (const float4*)(projS + w * 256);
        const float4* bb4 = (const float4*)bufS;
        const float4* al4 = (const float4*)alpha;
        const int wsh = 4 * (lane & 7);
        const int widx = lane >> 3;
        const float sg0 = (lane & 1) ? -1.f : 1.f;
        const float sg1 = (lane & 2) ? -1.f : 1.f;
        const float sg2 = (lane & 4) ? -1.f : 1.f;
        const float sg3 = (lane & 8) ? -1.f : 1.f;
        const float sg4 = (lane & 16) ? -1.f : 1.f;
        float partial = 0.f;

        const float4 xa4 = pj4[lane];        // invariant over j
        const float4 xb4 = pj4[lane + 32];

        #pragma unroll 1
        for (int j = 0; j < 32; ++j) {
            unsigned n0 = dbitsS[j * 8 + widx] >> wsh;
            unsigned n1 = dbitsS[j * 8 + 4 + widx] >> wsh;
            float x0 = __uint_as_float(__float_as_uint(xa4.x) ^ ((n0 << 31) & 0x80000000u));
            float x1 = __uint_as_float(__float_as_uint(xa4.y) ^ ((n0 << 30) & 0x80000000u));
            float x2 = __uint_as_float(__float_as_uint(xa4.z) ^ ((n0 << 29) & 0x80000000u));
            float x3 = __uint_as_float(__float_as_uint(xa4.w) ^ ((n0 << 28) & 0x80000000u));
            float x4 = __uint_as_float(__float_as_uint(xb4.x) ^ ((n1 << 31) & 0x80000000u));
            float x5 = __uint_as_float(__float_as_uint(xb4.y) ^ ((n1 << 30) & 0x80000000u));
            float x6 = __uint_as_float(__float_as_uint(xb4.z) ^ ((n1 << 29) & 0x80000000u));
            float x7 = __uint_as_float(__float_as_uint(xb4.w) ^ ((n1 << 28) & 0x80000000u));

            // register butterflies: h=1, h=2, h=128
            BFLY(x0, x1); BFLY(x2, x3); BFLY(x4, x5); BFLY(x6, x7);
            BFLY(x0, x2); BFLY(x1, x3); BFLY(x4, x6); BFLY(x5, x7);
            BFLY(x0, x4); BFLY(x1, x5); BFLY(x2, x6); BFLY(x3, x7);

            // cross-lane butterflies: h = 4,8,16,32,64
            #define SSTAGE(m, sg)                                                  \
                x0 = fmaf(x0, sg, __shfl_xor_sync(0xffffffffu, x0, m));            \
                x1 = fmaf(x1, sg, __shfl_xor_sync(0xffffffffu, x1, m));            \
                x2 = fmaf(x2, sg, __shfl_xor_sync(0xffffffffu, x2, m));            \
                x3 = fmaf(x3, sg, __shfl_xor_sync(0xffffffffu, x3, m));            \
                x4 = fmaf(x4, sg, __shfl_xor_sync(0xffffffffu, x4, m));            \
                x5 = fmaf(x5, sg, __shfl_xor_sync(0xffffffffu, x5, m));            \
                x6 = fmaf(x6, sg, __shfl_xor_sync(0xffffffffu, x6, m));            \
                x7 = fmaf(x7, sg, __shfl_xor_sync(0xffffffffu, x7, m));
            SSTAGE(1, sg0) SSTAGE(2, sg1) SSTAGE(4, sg2) SSTAGE(8, sg3) SSTAGE(16, sg4)
            #undef SSTAGE

            float4 b0 = bb4[j * 64 + lane];
            float4 b1 = bb4[j * 64 + 32 + lane];
            float4 a0 = __ldg(&al4[j * 64 + lane]);
            float4 a1 = __ldg(&al4[j * 64 + 32 + lane]);
            partial = fmaf(__cosf(x0 + b0.x), a0.x, partial);
            partial = fmaf(__cosf(x1 + b0.y), a0.y, partial);
            partial = fmaf(__cosf(x2 + b0.z), a0.z, partial);
            partial = fmaf(__cosf(x3 + b0.w), a0.w, partial);
            partial = fmaf(__cosf(x4 + b1.x), a1.x, partial);
            partial = fmaf(__cosf(x5 + b1.y), a1.y, partial);
            partial = fmaf(__cosf(x6 + b1.z), a1.z, partial);
            partial = fmaf(__cosf(x7 + b1.w), a1.w, partial);
        }

        #pragma unroll
        for (int o = 16; o; o >>= 1) partial += __shfl_xor_sync(0xffffffffu, partial, o);
        if (lane == 0) {
            int atom = atomsS[w];
            atomicAdd(&out[atom >> 6], partial * 0.015625f);  // FEAT_NORM = 1/64
        }
    }
}

extern "C" void kernel_launch(void* const* d_in, const int* in_sizes, int n_in,
                              void* d_out, int out_size) {
    (void)in_sizes; (void)n_in; (void)out_size;
    const float* rep       = (const float*)d_in[0];
    const int*   charges   = (const int*)d_in[1];
    const float* reductors = (const float*)d_in[2];
    const float* Dmat      = (const float*)d_in[3];
    const float* bias      = (const float*)d_in[4];
    const float* alpha     = (const float*)d_in[5];
    float* out = (float*)d_out;

    prep_kernel<<<1, 128>>>(charges, out);
    sorf_kernel<<<dim3(NBLK, 4), 256>>>(rep, reductors, Dmat, bias, alpha, out);
}

// round 6
// speedup vs baseline: 1.8434x; 1.7089x over previous
#include <cuda_runtime.h>

// SORF fused: out[m] = (1/64) * sum_a alpha . cos( (1/16) H (D_s ⊙ (rep[m,a] @ red[s])) + bias_s ),
// s = charges[m,a]. Atoms grouped by charge. 512-thread fused kernel:
//   phase 1: GEMV proj = rep @ red[s]  (f32x2 FMA, split-r, prefetch pipeline)
//   phase 2: warp = (atom, j-half); FWHT(256) in registers+shfl, cos-dot, smem-resident.

#define ATOMS 8
#define NATOMS 2048           // M*A
#define NCHUNK (NATOMS / ATOMS)

__device__ int g_count[4];
__device__ int g_list[4 * NATOMS];

// ---- prep: smem-staged charges, warp-ballot compaction ----
__global__ void prep_kernel(const int* __restrict__ charges, float* __restrict__ out) {
    __shared__ int chS[NATOMS];
    const int tid = threadIdx.x;          // 256 threads
    if (tid < 32) out[tid] = 0.0f;
    #pragma unroll
    for (int i = 0; i < NATOMS / 256; ++i) chS[tid + 256 * i] = charges[tid + 256 * i];
    __syncthreads();
    const int lane = tid & 31;
    const int w = tid >> 5;               // warp w handles charge s = w
    if (w >= 4) return;
    int cnt = 0;
    const unsigned lt = (1u << lane) - 1u;
    #pragma unroll 1
    for (int base = 0; base < NATOMS; base += 32) {
        int c = chS[base + lane];
        unsigned m = __ballot_sync(0xffffffffu, c == w);
        if (c == w) g_list[w * NATOMS + cnt + __popc(m & lt)] = base + lane;
        cnt += __popc(m);
    }
    if (lane == 0) g_count[w] = cnt;
}

typedef unsigned long long ull;
__device__ __forceinline__ void ffma2(ull& acc, ull a, ull b) {
    asm("fma.rn.f32x2 %0, %1, %2, %0;" : "+l"(acc) : "l"(a), "l"(b));
}
__device__ __forceinline__ ull pack2(float a, float b) {
    ull r; asm("mov.b64 %0, {%1, %2};" : "=l"(r) : "f"(a), "f"(b)); return r;
}
__device__ __forceinline__ float2 unpack2(ull v) {
    float2 r; asm("mov.b64 {%0, %1}, %2;" : "=f"(r.x), "=f"(r.y) : "l"(v)); return r;
}

#define BFLY(a, b) do { float t_ = (a); (a) = t_ + (b); (b) = t_ - (b); } while (0)

__global__ void __launch_bounds__(512) sorf_kernel(
    const float* __restrict__ rep,
    const float* __restrict__ reductors,
    const float* __restrict__ Dmat,
    const float* __restrict__ bias,
    const float* __restrict__ alpha,
    float* __restrict__ out)
{
    const int s = blockIdx.y;
    const int n = g_count[s];
    const int start = blockIdx.x * ATOMS;
    if (start >= n) return;
    const int cnt = min(ATOMS, n - start);

    // 32 KB region: phase 1 = duplicated rep pairs {v,v}; phase 2 = bias (overlaid)
    __shared__ __align__(16) char bufS[ATOMS * 512 * 8];
    __shared__ float projS[ATOMS * 256];      // 8 KB
    __shared__ unsigned dbitsS[256];          // sign bits: 32 stacks x 8 words
    __shared__ int atomsS[ATOMS];
    __shared__ float wpartS[ATOMS];

    const int tid = threadIdx.x;
    const int lane = tid & 31;
    const int w = tid >> 5;                   // 16 warps

    if (tid < ATOMS) atomsS[tid] = (tid < cnt) ? g_list[s * NATOMS + start + tid] : -1;
    __syncthreads();

    // fill duplicated rep tile: repdup[atom][r] = {rep_r, rep_r}
    {
        ull* repdup = (ull*)bufS;
        const float4* src = (const float4*)rep;
        #pragma unroll
        for (int it = 0; it < 2; ++it) {
            int idx = tid + 512 * it;            // 1024 float4 slots = 8 atoms * 128
            int ai = idx >> 7, q = idx & 127;
            int atom = atomsS[ai];
            float4 v = (atom >= 0) ? src[(size_t)atom * 128 + q] : make_float4(0.f, 0.f, 0.f, 0.f);
            ull* d = repdup + ai * 512 + q * 4;
            d[0] = pack2(v.x, v.x); d[1] = pack2(v.y, v.y);
            d[2] = pack2(v.z, v.z); d[3] = pack2(v.w, v.w);
        }
    }
    __syncthreads();

    // ---------------- Phase 1: proj = (1/16) * rep @ red[s]
    // thread = (c2: 128 col-pairs, rh: 2 row-halves, ag: 2 atom-quads); 256 rows each.
    const int c2 = tid & 127;
    const int rh = (tid >> 7) & 1;
    const int ag = tid >> 8;
    ull acc[4] = {0ull, 0ull, 0ull, 0ull};
    {
        const ull* rbase = (const ull*)reductors + (size_t)s * 65536 + rh * 32768 + c2;
        const ulonglong2* rp = (const ulonglong2*)bufS;

        ull buf0[4], buf1[4];
        #pragma unroll
        for (int k = 0; k < 4; ++k) buf0[k] = rbase[(size_t)k * 128];
        #pragma unroll
        for (int k = 0; k < 4; ++k) buf1[k] = rbase[(size_t)(4 + k) * 128];

        #pragma unroll 1
        for (int r = 0; r < 256; r += 8) {
            ull c0[4], c1[4];
            #pragma unroll
            for (int k = 0; k < 4; ++k) c0[k] = buf0[k];
            if (r + 8 < 256) {
                #pragma unroll
                for (int k = 0; k < 4; ++k) buf0[k] = rbase[(size_t)(r + 8 + k) * 128];
            }
            #pragma unroll
            for (int a = 0; a < 4; ++a) {
                int base = (ag * 4 + a) * 256 + rh * 128 + (r >> 1);
                ulonglong2 p0 = rp[base];
                ulonglong2 p1 = rp[base + 1];
                ffma2(acc[a], p0.x, c0[0]); ffma2(acc[a], p0.y, c0[1]);
                ffma2(acc[a], p1.x, c0[2]); ffma2(acc[a], p1.y, c0[3]);
            }
            #pragma unroll
            for (int k = 0; k < 4; ++k) c1[k] = buf1[k];
            if (r + 12 < 256) {
                #pragma unroll
                for (int k = 0; k < 4; ++k) buf1[k] = rbase[(size_t)(r + 12 + k) * 128];
            }
            #pragma unroll
            for (int a = 0; a < 4; ++a) {
                int base = (ag * 4 + a) * 256 + rh * 128 + ((r + 4) >> 1);
                ulonglong2 p0 = rp[base];
                ulonglong2 p1 = rp[base + 1];
                ffma2(acc[a], p0.x, c1[0]); ffma2(acc[a], p0.y, c1[1]);
                ffma2(acc[a], p1.x, c1[2]); ffma2(acc[a], p1.y, c1[3]);
            }
        }
        // rh==0 writes raw partials before the barrier
        if (rh == 0) {
            #pragma unroll
            for (int a = 0; a < 4; ++a) {
                float2 v = unpack2(acc[a]);
                ((float2*)projS)[(ag * 4 + a) * 128 + c2] = v;
            }
        }
    }
    __syncthreads();   // repdup reads done; rh0 partials visible

    // rh==1 combines + scales; meanwhile bias overlay + dbits by all threads
    if (rh == 1) {
        #pragma unroll
        for (int a = 0; a < 4; ++a) {
            int idx = (ag * 4 + a) * 128 + c2;
            float2 p = ((float2*)projS)[idx];
            float2 m = unpack2(acc[a]);
            ((float2*)projS)[idx] = make_float2((p.x + m.x) * 0.0625f, (p.y + m.y) * 0.0625f);
        }
    }
    {
        float4* dst = (float4*)bufS;
        const float4* src = (const float4*)(bias + (size_t)s * 8192);
        #pragma unroll
        for (int it = 0; it < 4; ++it) dst[tid + 512 * it] = src[tid + 512 * it];
        const float* dsrc = Dmat + (size_t)s * 8192;
        #pragma unroll 1
        for (int k = 0; k < 16; ++k) {           // 16 warps x 16 words = 256
            int word = w * 16 + k;
            float dv = dsrc[word * 32 + lane];
            unsigned b = __ballot_sync(0xffffffffu, dv < 0.0f);
            if (lane == 0) dbitsS[word] = b;
        }
    }
    __syncthreads();

    // ---------------- Phase 2: warp = (atom ai, j-half jh); 16 stacks each
    // x[c] holds p = 4*lane+c ; x[4+c] holds p = 128+4*lane+c
    const int ai = w >> 1;
    const int jh = w & 1;
    const int atom = atomsS[ai];
    float partial = 0.f;

    if (atom >= 0) {
        const float4* pj4 = (const float4*)(projS + ai * 256);
        const float4* bb4 = (const float4*)bufS;
        const float4* al4 = (const float4*)alpha;
        const int wsh = 4 * (lane & 7);
        const int widx = lane >> 3;
        const float sg0 = (lane & 1) ? -1.f : 1.f;
        const float sg1 = (lane & 2) ? -1.f : 1.f;
        const float sg2 = (lane & 4) ? -1.f : 1.f;
        const float sg3 = (lane & 8) ? -1.f : 1.f;
        const float sg4 = (lane & 16) ? -1.f : 1.f;

        const float4 xa4 = pj4[lane];        // invariant over j
        const float4 xb4 = pj4[lane + 32];

        #pragma unroll 1
        for (int j = 16 * jh; j < 16 * jh + 16; ++j) {
            unsigned n0 = dbitsS[j * 8 + widx] >> wsh;
            unsigned n1 = dbitsS[j * 8 + 4 + widx] >> wsh;
            float x0 = __uint_as_float(__float_as_uint(xa4.x) ^ ((n0 << 31) & 0x80000000u));
            float x1 = __uint_as_float(__float_as_uint(xa4.y) ^ ((n0 << 30) & 0x80000000u));
            float x2 = __uint_as_float(__float_as_uint(xa4.z) ^ ((n0 << 29) & 0x80000000u));
            float x3 = __uint_as_float(__float_as_uint(xa4.w) ^ ((n0 << 28) & 0x80000000u));
            float x4 = __uint_as_float(__float_as_uint(xb4.x) ^ ((n1 << 31) & 0x80000000u));
            float x5 = __uint_as_float(__float_as_uint(xb4.y) ^ ((n1 << 30) & 0x80000000u));
            float x6 = __uint_as_float(__float_as_uint(xb4.z) ^ ((n1 << 29) & 0x80000000u));
            float x7 = __uint_as_float(__float_as_uint(xb4.w) ^ ((n1 << 28) & 0x80000000u));

            // register butterflies: h=1, h=2, h=128
            BFLY(x0, x1); BFLY(x2, x3); BFLY(x4, x5); BFLY(x6, x7);
            BFLY(x0, x2); BFLY(x1, x3); BFLY(x4, x6); BFLY(x5, x7);
            BFLY(x0, x4); BFLY(x1, x5); BFLY(x2, x6); BFLY(x3, x7);

            // cross-lane butterflies: h = 4,8,16,32,64
            #define SSTAGE(m, sg)                                                  \
                x0 = fmaf(x0, sg, __shfl_xor_sync(0xffffffffu, x0, m));            \
                x1 = fmaf(x1, sg, __shfl_xor_sync(0xffffffffu, x1, m));            \
                x2 = fmaf(x2, sg, __shfl_xor_sync(0xffffffffu, x2, m));            \
                x3 = fmaf(x3, sg, __shfl_xor_sync(0xffffffffu, x3, m));            \
                x4 = fmaf(x4, sg, __shfl_xor_sync(0xffffffffu, x4, m));            \
                x5 = fmaf(x5, sg, __shfl_xor_sync(0xffffffffu, x5, m));            \
                x6 = fmaf(x6, sg, __shfl_xor_sync(0xffffffffu, x6, m));            \
                x7 = fmaf(x7, sg, __shfl_xor_sync(0xffffffffu, x7, m));
            SSTAGE(1, sg0) SSTAGE(2, sg1) SSTAGE(4, sg2) SSTAGE(8, sg3) SSTAGE(16, sg4)
            #undef SSTAGE

            float4 b0 = bb4[j * 64 + lane];
            float4 b1 = bb4[j * 64 + 32 + lane];
            float4 a0 = __ldg(&al4[j * 64 + lane]);
            float4 a1 = __ldg(&al4[j * 64 + 32 + lane]);
            partial = fmaf(__cosf(x0 + b0.x), a0.x, partial);
            partial = fmaf(__cosf(x1 + b0.y), a0.y, partial);
            partial = fmaf(__cosf(x2 + b0.z), a0.z, partial);
            partial = fmaf(__cosf(x3 + b0.w), a0.w, partial);
            partial = fmaf(__cosf(x4 + b1.x), a1.x, partial);
            partial = fmaf(__cosf(x5 + b1.y), a1.y, partial);
            partial = fmaf(__cosf(x6 + b1.z), a1.z, partial);
            partial = fmaf(__cosf(x7 + b1.w), a1.w, partial);
        }

        #pragma unroll
        for (int o = 16; o; o >>= 1) partial += __shfl_xor_sync(0xffffffffu, partial, o);
    }

    if (jh == 1 && lane == 0) wpartS[ai] = partial;
    __syncthreads();
    if (jh == 0 && lane == 0 && atom >= 0)
        atomicAdd(&out[atom >> 6], (partial + wpartS[ai]) * 0.015625f);  // FEAT_NORM = 1/64
}

extern "C" void kernel_launch(void* const* d_in, const int* in_sizes, int n_in,
                              void* d_out, int out_size) {
    (void)in_sizes; (void)n_in; (void)out_size;
    const float* rep       = (const float*)d_in[0];
    const int*   charges   = (const int*)d_in[1];
    const float* reductors = (const float*)d_in[2];
    const float* Dmat      = (const float*)d_in[3];
    const float* bias      = (const float*)d_in[4];
    const float* alpha     = (const float*)d_in[5];
    float* out = (float*)d_out;

    prep_kernel<<<1, 256>>>(charges, out);
    sorf_kernel<<<dim3(NCHUNK, 4), 512>>>(rep, reductors, Dmat, bias, alpha, out);
}